// round 15
// baseline (speedup 1.0000x reference)
#include <cuda_runtime.h>
#include <cuda_fp16.h>
#include <stdint.h>
#include <math.h>
typedef __half f16;

__device__ __align__(256) f16 gX1[(size_t)131072*1024];
__device__ __align__(256) f16 gX2[(size_t)131072*1024];
__device__ __align__(256) f16 gW1[1024*64];
__device__ __align__(256) f16 gW2[1024*1024];
__device__ __align__(256) f16 gQ1[256*1024];
__device__ __align__(256) f16 gQ2[128*256];

__device__ __forceinline__ uint32_t smem_u32(const void* p) {
    uint32_t a; asm("{ .reg .u64 t; cvta.to.shared.u64 t, %1; cvt.u32.u64 %0, t; }" : "=r"(a) : "l"(p));
    return a;
}
__device__ __forceinline__ void cpa16(uint32_t d, const void* s) {
    asm volatile("cp.async.cg.shared.global [%0], [%1], 16;" :: "r"(d), "l"(s));
}
#define CP_COMMIT() asm volatile("cp.async.commit_group;" ::: "memory")
#define CP_WAIT(n)  asm volatile("cp.async.wait_group %0;" :: "n"(n) : "memory")
__device__ __forceinline__ void ldm4(uint32_t* r, uint32_t a) {
    asm volatile("ldmatrix.sync.aligned.m8n8.x4.shared.b16 {%0,%1,%2,%3}, [%4];"
        : "=r"(r[0]), "=r"(r[1]), "=r"(r[2]), "=r"(r[3]) : "r"(a));
}
__device__ __forceinline__ void mma_f16(float* c, const uint32_t* a, const uint32_t* b) {
    asm volatile("mma.sync.aligned.m16n8k16.row.col.f32.f16.f16.f32 "
        "{%0,%1,%2,%3}, {%4,%5,%6,%7}, {%8,%9}, {%0,%1,%2,%3};"
        : "+f"(c[0]), "+f"(c[1]), "+f"(c[2]), "+f"(c[3])
        : "r"(a[0]), "r"(a[1]), "r"(a[2]), "r"(a[3]), "r"(b[0]), "r"(b[1]));
}
#define SWZ(x) ((x) ^ (((x) >> 3) & 0x70))
__device__ __forceinline__ uint32_t a_addr(uint32_t base, int r0, int kk, int lane) {
    return base + SWZ((r0 + (lane & 15)) * 128 + kk * 32 + ((lane >> 4) << 4));
}
__device__ __forceinline__ uint32_t b_addr(uint32_t base, int n0, int kk, int lane) {
    return base + SWZ((n0 + (lane & 7) + ((lane >> 4) << 3)) * 128 + kk * 32 + (((lane >> 3) & 1) << 4));
}
template<int R, int T>
__device__ __forceinline__ void cp_tile(uint32_t dsm, const f16* g, long row0, int stride, int k0, int tid) {
    #pragma unroll
    for (int i = 0; i < R * 8 / T; ++i) {
        int u = tid + i * T, r = u >> 3, c = u & 7;
        cpa16(dsm + SWZ(r * 128 + c * 16), g + (row0 + r) * (long)stride + k0 + c * 8);
    }
}
__device__ __forceinline__ uint32_t pack_h2(f16 a, f16 b) {
    __half2 t; t.x = a; t.y = b; return *reinterpret_cast<uint32_t*>(&t);
}
__device__ __forceinline__ float acc_tanh(float x) {
    float e = expf(2.0f * x);
    return 1.0f - 2.0f / (e + 1.0f);
}
template<int MF, int NP, int KK>
__device__ __forceinline__ void mma_chunkG(float (&c)[MF][NP*2][4], uint32_t bA, uint32_t bB,
                                           int m0, int n0, int lane) {
    #pragma unroll
    for (int kk = 0; kk < KK; ++kk) {
        uint32_t A[MF][4];
        #pragma unroll
        for (int mf = 0; mf < MF; ++mf) ldm4(A[mf], a_addr(bA, m0 + mf * 16, kk, lane));
        #pragma unroll
        for (int np = 0; np < NP; ++np) {
            uint32_t B[4];
            ldm4(B, b_addr(bB, n0 + np * 16, kk, lane));
            #pragma unroll
            for (int mf = 0; mf < MF; ++mf)
                #pragma unroll
                for (int h = 0; h < 2; ++h)
                    mma_f16(c[mf][np * 2 + h], A[mf], B + h * 2);
        }
    }
}
__device__ __forceinline__ void epi_store(float (&c)[2][8][4], int m0, int gcol0, int lane,
        long grow0, const float* bias, const float* gate, f16* gout) {
    int t4 = lane >> 2, q = lane & 3;
    #pragma unroll
    for (int mf = 0; mf < 2; ++mf)
    #pragma unroll
    for (int s = 0; s < 2; ++s) {
        long gr = (grow0 + m0 + mf * 16 + s * 8 + t4) * 1024;
        #pragma unroll
        for (int nf = 0; nf < 8; ++nf) {
            int col = gcol0 + nf * 8 + q * 2;
            float g = gate[col >> 5];
            float v0 = acc_tanh(c[mf][nf][s * 2]     + bias[col])     * g;
            float v1 = acc_tanh(c[mf][nf][s * 2 + 1] + bias[col + 1]) * g;
            *(uint32_t*)(gout + gr + col) = pack_h2(__float2half_rn(v0), __float2half_rn(v1));
        }
    }
}

__global__ void prep(const float* __restrict__ W1, const float* __restrict__ W2,
                     const float* __restrict__ Wq1, const float* __restrict__ Wq2) {
    int gt = blockIdx.x * blockDim.x + threadIdx.x, gs = gridDim.x * blockDim.x;
    for (int i = gt; i < 1024 * 1024; i += gs) {
        int n = i >> 10, k = i & 1023;
        gW2[i] = __float2half_rn(W2[(size_t)(n >> 5) * 32768 + k * 32 + (n & 31)]);
    }
    for (int i = gt; i < 256 * 1024; i += gs) {
        int qq = i >> 10, n = i & 1023;
        gQ1[i] = __float2half_rn(Wq1[n * 256 + qq]);
    }
    for (int i = gt; i < 128 * 256; i += gs) {
        int o = i >> 8, qq = i & 255;
        gQ2[i] = __float2half_rn(Wq2[qq * 128 + o]);
    }
    for (int i = gt; i < 1024 * 64; i += gs) {
        int n = i >> 6, d = i & 63;
        gW1[i] = __float2half_rn((d < 32) ? W1[(n >> 5) * 1024 + d * 32 + (n & 31)] : 0.0f);
    }
}

// ---- k1: X0[128][64] at 0 (16KB), W buf 2x16KB at 16384, b1s 49152, g1s 53248
#define K1_B1S 49152
#define K1_G1S 53248
#define K1_SZ  53376
__global__ __launch_bounds__(256,2) void k1(const float* __restrict__ state, const float* __restrict__ action,
                                            const float* __restrict__ b1, const float* __restrict__ g1) {
    extern __shared__ char smx[];
    const uint32_t sb = smem_u32(smx);
    const int tid = threadIdx.x, lane = tid & 31, wid = tid >> 5;
    const long row0 = (long)blockIdx.x * 128;
    float* b1s = (float*)(smx + K1_B1S);
    float* g1s = (float*)(smx + K1_G1S);
    for (int i = tid; i < 1024; i += 256) b1s[i] = __ldg(b1 + i);
    if (tid < 32) g1s[tid] = 1.f / (1.f + expf(-__ldg(g1 + tid)));
    for (int i = tid; i < 4096; i += 256) ((uint32_t*)smx)[i] = 0;
    __syncthreads();
    for (int i = tid; i < 4096; i += 256) {
        int r = i >> 5, d = i & 31;
        float v = (d < 24) ? __ldg(state + (row0 + r) * 24 + d)
                           : __ldg(action + (row0 + r) * 8 + (d - 24));
        *(f16*)(smx + SWZ(r * 128 + d * 2)) = __float2half_rn(v);
    }
    __syncthreads();
    const int m0 = (wid & 3) * 32, n0 = (wid >> 2) * 64;
    cp_tile<128,256>(sb + 16384, gW1, 0, 64, 0, tid);
    CP_COMMIT();
    #pragma unroll 1
    for (int nt = 0; nt < 8; ++nt) {
        CP_WAIT(0);
        __syncthreads();
        if (nt + 1 < 8) {
            cp_tile<128,256>(sb + 16384 + ((nt + 1) & 1) * 16384, gW1, (long)(nt + 1) * 128, 64, 0, tid);
            CP_COMMIT();
        }
        uint32_t bs = sb + 16384 + (nt & 1) * 16384;
        float c[2][8][4];
        #pragma unroll
        for (int a = 0; a < 2; ++a)
            #pragma unroll
            for (int b = 0; b < 8; ++b)
                #pragma unroll
                for (int e = 0; e < 4; ++e) c[a][b][e] = 0.f;
        mma_chunkG<2,4,2>(c, sb, bs, m0, n0, lane);
        epi_store(c, m0, nt * 128 + n0, lane, row0, b1s, g1s, gX1);
    }
}

// ---- k2: 512 threads, tile 128x256, 4 stages x 48KB (A 16K + B 32K)
#define K2_B2S 196608
#define K2_G2S 200704
#define K2_SZ  200832
__global__ __launch_bounds__(512,1) void k2(const float* __restrict__ b2, const float* __restrict__ g2) {
    extern __shared__ char smx[];
    const uint32_t sb = smem_u32(smx);
    const int tid = threadIdx.x, lane = tid & 31, wid = tid >> 5;
    const long row0 = (long)(blockIdx.x >> 2) * 128;
    const int nt = blockIdx.x & 3;           // 256-col block
    float* b2s = (float*)(smx + K2_B2S);
    float* g2s = (float*)(smx + K2_G2S);
    for (int i = tid; i < 1024; i += 512) b2s[i] = __ldg(b2 + i);
    if (tid < 32) g2s[tid] = 1.f / (1.f + expf(-__ldg(g2 + tid)));
    const int m0 = (wid >> 2) * 32, n0 = (wid & 3) * 64;
    auto load = [&](int kc) {
        uint32_t st = sb + (kc & 3) * 49152;
        cp_tile<128,512>(st,         gX1, row0, 1024, kc * 64, tid);
        cp_tile<256,512>(st + 16384, gW2, (long)nt * 256, 1024, kc * 64, tid);
        CP_COMMIT();
    };
    load(0); load(1); load(2);
    float c[2][8][4];
    #pragma unroll
    for (int a = 0; a < 2; ++a)
        #pragma unroll
        for (int b = 0; b < 8; ++b)
            #pragma unroll
            for (int e = 0; e < 4; ++e) c[a][b][e] = 0.f;
    #pragma unroll 1
    for (int kc = 0; kc < 16; ++kc) {
        int rem = 15 - kc;
        if (rem >= 2) CP_WAIT(2); else if (rem == 1) CP_WAIT(1); else CP_WAIT(0);
        __syncthreads();
        if (kc + 3 < 16) load(kc + 3);
        uint32_t st = sb + (kc & 3) * 49152;
        mma_chunkG<2,4,4>(c, st, st + 16384, m0, n0, lane);
    }
    epi_store(c, m0, nt * 256 + n0, lane, row0, b2s, g2s, gX2);
}

// ---- k3: 256 threads, 4 stages x 48KB at 0..196608; post-loop reuse:
//      H1 64KB at 0 (stages 0/1), Q2 dbl buffer at 98304/114688 (stage 2); params 196608+
#define K3_H1  0
#define K3_Q2A 98304
#define K3_Q2B 114688
#define K3_BQ1 196608
#define K3_L1G 197632
#define K3_L1B 198656
#define K3_BQ2 199680
#define K3_L2G 200192
#define K3_L2B 200704
#define K3_W3  201216
#define K3_PS  201728
#define K3_PQ  203776
#define K3_MU  205824
#define K3_RS  206336
#define K3_PD  206848
#define K3_SZ  208896
__global__ __launch_bounds__(256,1) void k3(const float* __restrict__ bq1, const float* __restrict__ l1g, const float* __restrict__ l1b,
                                            const float* __restrict__ bq2, const float* __restrict__ l2g, const float* __restrict__ l2b,
                                            const float* __restrict__ wq3, const float* __restrict__ bq3, float* __restrict__ out) {
    extern __shared__ char smx[];
    const uint32_t sb = smem_u32(smx);
    const int tid = threadIdx.x, lane = tid & 31, wid = tid >> 5;
    const int t4 = lane >> 2, q = lane & 3;
    const long row0 = (long)blockIdx.x * 128;
    float* bq1s = (float*)(smx + K3_BQ1); float* l1gs = (float*)(smx + K3_L1G);
    float* l1bs = (float*)(smx + K3_L1B); float* bq2s = (float*)(smx + K3_BQ2);
    float* l2gs = (float*)(smx + K3_L2G); float* l2bs = (float*)(smx + K3_L2B);
    float* w3s  = (float*)(smx + K3_W3);
    float* PS = (float*)(smx + K3_PS); float* PQ = (float*)(smx + K3_PQ);
    float* MU = (float*)(smx + K3_MU); float* RS = (float*)(smx + K3_RS);
    float* PD = (float*)(smx + K3_PD);
    bq1s[tid] = __ldg(bq1 + tid); l1gs[tid] = __ldg(l1g + tid); l1bs[tid] = __ldg(l1b + tid);
    if (tid < 128) { bq2s[tid] = __ldg(bq2 + tid); l2gs[tid] = __ldg(l2g + tid);
                     l2bs[tid] = __ldg(l2b + tid); w3s[tid] = __ldg(wq3 + tid); }
    const int m0 = (wid & 1) * 64, n0 = (wid >> 1) * 64, wn = wid >> 1;
    auto load3 = [&](int kc) {
        uint32_t st = sb + (kc & 3) * 49152;
        cp_tile<128,256>(st,         gX2, row0, 1024, kc * 64, tid);
        cp_tile<256,256>(st + 16384, gQ1, 0, 1024, kc * 64, tid);
        CP_COMMIT();
    };
    load3(0); load3(1); load3(2);
    float c3[4][8][4];
    #pragma unroll
    for (int a = 0; a < 4; ++a)
        #pragma unroll
        for (int b = 0; b < 8; ++b)
            #pragma unroll
            for (int e = 0; e < 4; ++e) c3[a][b][e] = 0.f;
    #pragma unroll 1
    for (int kc = 0; kc < 16; ++kc) {
        int rem = 15 - kc;
        if (rem >= 2) CP_WAIT(2); else if (rem == 1) CP_WAIT(1); else CP_WAIT(0);
        __syncthreads();
        if (kc + 3 < 16) load3(kc + 3);
        uint32_t st = sb + (kc & 3) * 49152;
        mma_chunkG<4,4,4>(c3, st, st + 16384, m0, n0, lane);
    }
    // Q2 prologue into stage-2 region (chunk kc=14: all warps past iter-15 barrier)
    cp_tile<128,256>(sb + K3_Q2A, gQ2, 0, 256, 0, tid);
    CP_COMMIT();
    #pragma unroll
    for (int mf = 0; mf < 4; ++mf)
        #pragma unroll
        for (int nf = 0; nf < 8; ++nf)
            #pragma unroll
            for (int e = 0; e < 4; ++e)
                c3[mf][nf][e] += bq1s[n0 + nf * 8 + q * 2 + (e & 1)];
    #pragma unroll
    for (int mf = 0; mf < 4; ++mf)
        #pragma unroll
        for (int s = 0; s < 2; ++s) {
            float sm1 = 0.f, sq = 0.f;
            #pragma unroll
            for (int nf = 0; nf < 8; ++nf) {
                float v0 = c3[mf][nf][s*2], v1 = c3[mf][nf][s*2+1];
                sm1 += v0 + v1; sq += v0 * v0 + v1 * v1;
            }
            sm1 += __shfl_xor_sync(~0u, sm1, 1); sm1 += __shfl_xor_sync(~0u, sm1, 2);
            sq  += __shfl_xor_sync(~0u, sq, 1);  sq  += __shfl_xor_sync(~0u, sq, 2);
            if (q == 0) {
                int r = m0 + mf * 16 + s * 8 + t4;
                PS[wn * 128 + r] = sm1; PQ[wn * 128 + r] = sq;
            }
        }
    __syncthreads();
    if (tid < 128) {
        float S  = PS[tid] + PS[128 + tid] + PS[256 + tid] + PS[384 + tid];
        float Q2 = PQ[tid] + PQ[128 + tid] + PQ[256 + tid] + PQ[384 + tid];
        float mu = S * (1.f / 256.f);
        MU[tid] = mu; RS[tid] = rsqrtf(Q2 * (1.f / 256.f) - mu * mu + 1e-5f);
    }
    __syncthreads();
    #pragma unroll
    for (int mf = 0; mf < 4; ++mf)
        #pragma unroll
        for (int s = 0; s < 2; ++s) {
            int r = m0 + mf * 16 + s * 8 + t4;
            float mu = MU[r], rs = RS[r];
            #pragma unroll
            for (int nf = 0; nf < 8; ++nf) {
                int col = n0 + nf * 8 + q * 2;
                float v0 = fmaxf((c3[mf][nf][s*2]   - mu) * rs * l1gs[col]   + l1bs[col],   0.f);
                float v1 = fmaxf((c3[mf][nf][s*2+1] - mu) * rs * l1gs[col+1] + l1bs[col+1], 0.f);
                int off = K3_H1 + ((col >> 6) << 14) + SWZ(r * 128 + (col & 63) * 2);
                *(uint32_t*)(smx + off) = pack_h2(__float2half_rn(v0), __float2half_rn(v1));
            }
        }
    const int m4 = (wid & 3) * 32, n4 = (wid >> 2) * 64, wn4 = wid >> 2;
    float c4[2][8][4];
    #pragma unroll
    for (int a = 0; a < 2; ++a)
        #pragma unroll
        for (int b = 0; b < 8; ++b)
            #pragma unroll
            for (int e = 0; e < 4; ++e) c4[a][b][e] = 0.f;
    #pragma unroll 1
    for (int qc = 0; qc < 4; ++qc) {
        CP_WAIT(0);
        __syncthreads();      // qc=0 barrier also publishes the H1 smem writes above
        if (qc + 1 < 4) {
            cp_tile<128,256>(sb + K3_Q2A + ((qc + 1) & 1) * 16384, gQ2, 0, 256, (qc + 1) * 64, tid);
            CP_COMMIT();
        }
        mma_chunkG<2,4,4>(c4, sb + K3_H1 + qc * 16384, sb + K3_Q2A + (qc & 1) * 16384, m4, n4, lane);
    }
    #pragma unroll
    for (int mf = 0; mf < 2; ++mf)
        #pragma unroll
        for (int nf = 0; nf < 8; ++nf)
            #pragma unroll
            for (int e = 0; e < 4; ++e)
                c4[mf][nf][e] += bq2s[n4 + nf * 8 + q * 2 + (e & 1)];
    #pragma unroll
    for (int mf = 0; mf < 2; ++mf)
        #pragma unroll
        for (int s = 0; s < 2; ++s) {
            float sm1 = 0.f, sq = 0.f;
            #pragma unroll
            for (int nf = 0; nf < 8; ++nf) {
                float v0 = c4[mf][nf][s*2], v1 = c4[mf][nf][s*2+1];
                sm1 += v0 + v1; sq += v0 * v0 + v1 * v1;
            }
            sm1 += __shfl_xor_sync(~0u, sm1, 1); sm1 += __shfl_xor_sync(~0u, sm1, 2);
            sq  += __shfl_xor_sync(~0u, sq, 1);  sq  += __shfl_xor_sync(~0u, sq, 2);
            if (q == 0) {
                int r = m4 + mf * 16 + s * 8 + t4;
                PS[wn4 * 128 + r] = sm1; PQ[wn4 * 128 + r] = sq;
            }
        }
    __syncthreads();
    if (tid < 128) {
        float S  = PS[tid] + PS[128 + tid];
        float Q2 = PQ[tid] + PQ[128 + tid];
        float mu = S * (1.f / 128.f);
        MU[tid] = mu; RS[tid] = rsqrtf(Q2 * (1.f / 128.f) - mu * mu + 1e-5f);
    }
    __syncthreads();
    #pragma unroll
    for (int mf = 0; mf < 2; ++mf)
        #pragma unroll
        for (int s = 0; s < 2; ++s) {
            int r = m4 + mf * 16 + s * 8 + t4;
            float mu = MU[r], rs = RS[r];
            float d = 0.f;
            #pragma unroll
            for (int nf = 0; nf < 8; ++nf) {
                int col = n4 + nf * 8 + q * 2;
                float v0 = fmaxf((c4[mf][nf][s*2]   - mu) * rs * l2gs[col]   + l2bs[col],   0.f);
                float v1 = fmaxf((c4[mf][nf][s*2+1] - mu) * rs * l2gs[col+1] + l2bs[col+1], 0.f);
                d += v0 * w3s[col] + v1 * w3s[col + 1];
            }
            d += __shfl_xor_sync(~0u, d, 1); d += __shfl_xor_sync(~0u, d, 2);
            if (q == 0) PD[wn4 * 128 + r] = d;
        }
    __syncthreads();
    if (tid < 128) out[row0 + tid] = PD[tid] + PD[128 + tid] + __ldg(bq3);
}

extern "C" void kernel_launch(void* const* d_in, const int* in_sizes, int n_in,
                              void* d_out, int out_size) {
    const float* state  = (const float*)d_in[0];
    const float* action = (const float*)d_in[1];
    const float* W1  = (const float*)d_in[2];
    const float* b1  = (const float*)d_in[3];
    const float* g1  = (const float*)d_in[4];
    const float* W2  = (const float*)d_in[5];
    const float* b2  = (const float*)d_in[6];
    const float* g2  = (const float*)d_in[7];
    const float* Wq1 = (const float*)d_in[8];
    const float* bq1 = (const float*)d_in[9];
    const float* l1g = (const float*)d_in[10];
    const float* l1b = (const float*)d_in[11];
    const float* Wq2 = (const float*)d_in[12];
    const float* bq2 = (const float*)d_in[13];
    const float* l2g = (const float*)d_in[14];
    const float* l2b = (const float*)d_in[15];
    const float* Wq3 = (const float*)d_in[16];
    const float* bq3 = (const float*)d_in[17];
    float* out = (float*)d_out;
    int B = in_sizes[0] / 24;
    int tiles = B / 128;
    cudaFuncSetAttribute(k1, cudaFuncAttributeMaxDynamicSharedMemorySize, K1_SZ);
    cudaFuncSetAttribute(k2, cudaFuncAttributeMaxDynamicSharedMemorySize, K2_SZ);
    cudaFuncSetAttribute(k3, cudaFuncAttributeMaxDynamicSharedMemorySize, K3_SZ);
    prep<<<256, 256>>>(W1, W2, Wq1, Wq2);
    k1<<<tiles, 256, K1_SZ>>>(state, action, b1, g1);
    k2<<<tiles * 4, 512, K2_SZ>>>(b2, g2);
    k3<<<tiles, 256, K3_SZ>>>(bq1, l1g, l1b, bq2, l2g, l2b, Wq3, bq3, out);
}

// round 16
// speedup vs baseline: 1.1396x; 1.1396x over previous
#include <cuda_runtime.h>
#include <cuda_fp16.h>
#include <stdint.h>
#include <math.h>
typedef __half f16;

__device__ __align__(256) f16 gX1[(size_t)131072*1024];
__device__ __align__(256) f16 gX2[(size_t)131072*1024];
__device__ __align__(256) f16 gW1[1024*64];
__device__ __align__(256) f16 gW2[1024*1024];
__device__ __align__(256) f16 gQ1[256*1024];
__device__ __align__(256) f16 gQ2[128*256];

__device__ __forceinline__ uint32_t smem_u32(const void* p) {
    uint32_t a; asm("{ .reg .u64 t; cvta.to.shared.u64 t, %1; cvt.u32.u64 %0, t; }" : "=r"(a) : "l"(p));
    return a;
}
__device__ __forceinline__ void cpa16(uint32_t d, const void* s) {
    asm volatile("cp.async.cg.shared.global [%0], [%1], 16;" :: "r"(d), "l"(s));
}
#define CP_COMMIT() asm volatile("cp.async.commit_group;" ::: "memory")
#define CP_WAIT(n)  asm volatile("cp.async.wait_group %0;" :: "n"(n) : "memory")
__device__ __forceinline__ void ldm4(uint32_t* r, uint32_t a) {
    asm volatile("ldmatrix.sync.aligned.m8n8.x4.shared.b16 {%0,%1,%2,%3}, [%4];"
        : "=r"(r[0]), "=r"(r[1]), "=r"(r[2]), "=r"(r[3]) : "r"(a));
}
__device__ __forceinline__ void mma_f16(float* c, const uint32_t* a, const uint32_t* b) {
    asm volatile("mma.sync.aligned.m16n8k16.row.col.f32.f16.f16.f32 "
        "{%0,%1,%2,%3}, {%4,%5,%6,%7}, {%8,%9}, {%0,%1,%2,%3};"
        : "+f"(c[0]), "+f"(c[1]), "+f"(c[2]), "+f"(c[3])
        : "r"(a[0]), "r"(a[1]), "r"(a[2]), "r"(a[3]), "r"(b[0]), "r"(b[1]));
}
#define SWZ(x) ((x) ^ (((x) >> 3) & 0x70))
__device__ __forceinline__ uint32_t a_addr(uint32_t base, int r0, int kk, int lane) {
    return base + SWZ((r0 + (lane & 15)) * 128 + kk * 32 + ((lane >> 4) << 4));
}
__device__ __forceinline__ uint32_t b_addr(uint32_t base, int n0, int kk, int lane) {
    return base + SWZ((n0 + (lane & 7) + ((lane >> 4) << 3)) * 128 + kk * 32 + (((lane >> 3) & 1) << 4));
}
template<int R>
__device__ __forceinline__ void cp_tile(uint32_t dsm, const f16* g, long row0, int stride, int k0, int tid) {
    #pragma unroll
    for (int i = 0; i < R * 8 / 256; ++i) {
        int u = tid + i * 256, r = u >> 3, c = u & 7;
        cpa16(dsm + SWZ(r * 128 + c * 16), g + (row0 + r) * (long)stride + k0 + c * 8);
    }
}
__device__ __forceinline__ uint32_t pack_h2(f16 a, f16 b) {
    __half2 t; t.x = a; t.y = b; return *reinterpret_cast<uint32_t*>(&t);
}
__device__ __forceinline__ float tanh_fast(float x) {
    float y; asm("tanh.approx.f32 %0, %1;" : "=f"(y) : "f"(x)); return y;
}
// single-pass fp16 MMA over one K64 slab (KK k-steps of 16)
template<int MF, int KK>
__device__ __forceinline__ void mma_chunk1(float (&c)[MF][8][4], uint32_t bA, uint32_t bB,
                                           int m0, int n0, int lane) {
    #pragma unroll
    for (int kk = 0; kk < KK; ++kk) {
        uint32_t A[MF][4];
        #pragma unroll
        for (int mf = 0; mf < MF; ++mf) ldm4(A[mf], a_addr(bA, m0 + mf * 16, kk, lane));
        #pragma unroll
        for (int np = 0; np < 4; ++np) {
            uint32_t B[4];
            ldm4(B, b_addr(bB, n0 + np * 16, kk, lane));
            #pragma unroll
            for (int mf = 0; mf < MF; ++mf)
                #pragma unroll
                for (int h = 0; h < 2; ++h)
                    mma_f16(c[mf][np * 2 + h], A[mf], B + h * 2);
        }
    }
}
__device__ __forceinline__ void epi_store(float (&c)[2][8][4], int m0, int gcol0, int lane,
        long grow0, const float* bias, const float* gate, f16* gout) {
    int t4 = lane >> 2, q = lane & 3;
    #pragma unroll
    for (int mf = 0; mf < 2; ++mf)
    #pragma unroll
    for (int s = 0; s < 2; ++s) {
        long gr = (grow0 + m0 + mf * 16 + s * 8 + t4) * 1024;
        #pragma unroll
        for (int nf = 0; nf < 8; ++nf) {
            int col = gcol0 + nf * 8 + q * 2;
            float g = gate[col >> 5];
            float v0 = tanh_fast(c[mf][nf][s * 2]     + bias[col])     * g;
            float v1 = tanh_fast(c[mf][nf][s * 2 + 1] + bias[col + 1]) * g;
            *(uint32_t*)(gout + gr + col) = pack_h2(__float2half_rn(v0), __float2half_rn(v1));
        }
    }
}

__global__ void prep(const float* __restrict__ W1, const float* __restrict__ W2,
                     const float* __restrict__ Wq1, const float* __restrict__ Wq2) {
    __shared__ float ts[32][33];
    int gt = blockIdx.x * blockDim.x + threadIdx.x, gs = gridDim.x * blockDim.x;
    int tid = threadIdx.x;
    // W2 -> gW2[n][k] via coalesced 32x32 smem transpose tiles
    for (int t = blockIdx.x; t < 1024; t += gridDim.x) {
        int kt = (t >> 5) * 32, nt_ = (t & 31) * 32;
        #pragma unroll
        for (int j = tid; j < 1024; j += 256) {
            int r = j >> 5, cn = j & 31;    // r = k-offset, cn = n-offset
            ts[r][cn] = W2[(size_t)(nt_ >> 5) * 32768 + (kt + r) * 32 + cn];
        }
        __syncthreads();
        #pragma unroll
        for (int j = tid; j < 1024; j += 256) {
            int rn = j >> 5, ck = j & 31;   // rn = n-offset, ck = k-offset
            gW2[(size_t)(nt_ + rn) * 1024 + kt + ck] = __float2half_rn(ts[ck][rn]);
        }
        __syncthreads();
    }
    for (int i = gt; i < 256 * 1024; i += gs) {
        int qq = i >> 10, n = i & 1023;
        gQ1[i] = __float2half_rn(Wq1[n * 256 + qq]);
    }
    for (int i = gt; i < 128 * 256; i += gs) {
        int o = i >> 8, qq = i & 255;
        gQ2[i] = __float2half_rn(Wq2[qq * 128 + o]);
    }
    for (int i = gt; i < 1024 * 64; i += gs) {
        int n = i >> 6, d = i & 63;
        gW1[i] = __float2half_rn((d < 32) ? W1[(n >> 5) * 1024 + d * 32 + (n & 31)] : 0.0f);
    }
}

// ---- k1: X0[128][64] at 0 (16KB), W buf 2x16KB at 16384, b1s 49152, g1s 53248
#define K1_B1S 49152
#define K1_G1S 53248
#define K1_SZ  53376
__global__ __launch_bounds__(256,2) void k1(const float* __restrict__ state, const float* __restrict__ action,
                                            const float* __restrict__ b1, const float* __restrict__ g1) {
    extern __shared__ char smx[];
    const uint32_t sb = smem_u32(smx);
    const int tid = threadIdx.x, lane = tid & 31, wid = tid >> 5;
    const long row0 = (long)blockIdx.x * 128;
    float* b1s = (float*)(smx + K1_B1S);
    float* g1s = (float*)(smx + K1_G1S);
    for (int i = tid; i < 1024; i += 256) b1s[i] = __ldg(b1 + i);
    if (tid < 32) g1s[tid] = 1.f / (1.f + expf(-__ldg(g1 + tid)));
    for (int i = tid; i < 4096; i += 256) ((uint32_t*)smx)[i] = 0;
    __syncthreads();
    for (int i = tid; i < 4096; i += 256) {
        int r = i >> 5, d = i & 31;
        float v = (d < 24) ? __ldg(state + (row0 + r) * 24 + d)
                           : __ldg(action + (row0 + r) * 8 + (d - 24));
        *(f16*)(smx + SWZ(r * 128 + d * 2)) = __float2half_rn(v);
    }
    __syncthreads();
    const int m0 = (wid & 3) * 32, n0 = (wid >> 2) * 64;
    cp_tile<128>(sb + 16384, gW1, 0, 64, 0, tid);
    CP_COMMIT();
    #pragma unroll 1
    for (int nt = 0; nt < 8; ++nt) {
        CP_WAIT(0);
        __syncthreads();
        if (nt + 1 < 8) {
            cp_tile<128>(sb + 16384 + ((nt + 1) & 1) * 16384, gW1, (long)(nt + 1) * 128, 64, 0, tid);
            CP_COMMIT();
        }
        uint32_t bs = sb + 16384 + (nt & 1) * 16384;
        float c[2][8][4];
        #pragma unroll
        for (int a = 0; a < 2; ++a)
            #pragma unroll
            for (int b = 0; b < 8; ++b)
                #pragma unroll
                for (int e = 0; e < 4; ++e) c[a][b][e] = 0.f;
        mma_chunk1<2, 2>(c, sb, bs, m0, n0, lane);
        epi_store(c, m0, nt * 128 + n0, lane, row0, b1s, g1s, gX1);
    }
}

// ---- k2: 3 stages x 32KB (A 16KB + B 16KB), b2s 98304, g2s 102400
#define K2_B2S 98304
#define K2_G2S 102400
#define K2_SZ  102528
__global__ __launch_bounds__(256,2) void k2(const float* __restrict__ b2, const float* __restrict__ g2) {
    extern __shared__ char smx[];
    const uint32_t sb = smem_u32(smx);
    const int tid = threadIdx.x, lane = tid & 31, wid = tid >> 5;
    const long row0 = (long)(blockIdx.x >> 3) * 128;
    const int nt = blockIdx.x & 7;
    float* b2s = (float*)(smx + K2_B2S);
    float* g2s = (float*)(smx + K2_G2S);
    for (int i = tid; i < 1024; i += 256) b2s[i] = __ldg(b2 + i);
    if (tid < 32) g2s[tid] = 1.f / (1.f + expf(-__ldg(g2 + tid)));
    const int m0 = (wid & 3) * 32, n0 = (wid >> 2) * 64;
    auto load = [&](int kc) {
        uint32_t st = sb + (kc % 3) * 32768;
        cp_tile<128>(st,         gX1, row0, 1024, kc * 64, tid);
        cp_tile<128>(st + 16384, gW2, (long)nt * 128, 1024, kc * 64, tid);
        CP_COMMIT();
    };
    load(0); load(1);
    float c[2][8][4];
    #pragma unroll
    for (int a = 0; a < 2; ++a)
        #pragma unroll
        for (int b = 0; b < 8; ++b)
            #pragma unroll
            for (int e = 0; e < 4; ++e) c[a][b][e] = 0.f;
    #pragma unroll 1
    for (int kc = 0; kc < 16; ++kc) {
        if (kc < 14) CP_WAIT(1); else CP_WAIT(0);
        __syncthreads();
        if (kc + 2 < 16) load(kc + 2);
        uint32_t st = sb + (kc % 3) * 32768;
        mma_chunk1<2, 4>(c, st, st + 16384, m0, n0, lane);
    }
    epi_store(c, m0, nt * 128 + n0, lane, row0, b2s, g2s, gX2);
}

// ---- k3: 3 stages x 48KB at 0..147456; H1 64KB at 147456;
//      Q2 double buffer inside old stage-1 region (sb+49152 / sb+65536); params at 212992+
#define K3_H1  147456
#define K3_Q2A 49152
#define K3_BQ1 212992
#define K3_L1G 214016
#define K3_L1B 215040
#define K3_BQ2 216064
#define K3_L2G 216576
#define K3_L2B 217088
#define K3_W3  217600
#define K3_PS  218112
#define K3_PQ  220160
#define K3_MU  222208
#define K3_RS  222720
#define K3_PD  223232
#define K3_SZ  225280
__global__ __launch_bounds__(256,1) void k3(const float* __restrict__ bq1, const float* __restrict__ l1g, const float* __restrict__ l1b,
                                            const float* __restrict__ bq2, const float* __restrict__ l2g, const float* __restrict__ l2b,
                                            const float* __restrict__ wq3, const float* __restrict__ bq3, float* __restrict__ out) {
    extern __shared__ char smx[];
    const uint32_t sb = smem_u32(smx);
    const int tid = threadIdx.x, lane = tid & 31, wid = tid >> 5;
    const int t4 = lane >> 2, q = lane & 3;
    const long row0 = (long)blockIdx.x * 128;
    float* bq1s = (float*)(smx + K3_BQ1); float* l1gs = (float*)(smx + K3_L1G);
    float* l1bs = (float*)(smx + K3_L1B); float* bq2s = (float*)(smx + K3_BQ2);
    float* l2gs = (float*)(smx + K3_L2G); float* l2bs = (float*)(smx + K3_L2B);
    float* w3s  = (float*)(smx + K3_W3);
    float* PS = (float*)(smx + K3_PS); float* PQ = (float*)(smx + K3_PQ);
    float* MU = (float*)(smx + K3_MU); float* RS = (float*)(smx + K3_RS);
    float* PD = (float*)(smx + K3_PD);
    bq1s[tid] = __ldg(bq1 + tid); l1gs[tid] = __ldg(l1g + tid); l1bs[tid] = __ldg(l1b + tid);
    if (tid < 128) { bq2s[tid] = __ldg(bq2 + tid); l2gs[tid] = __ldg(l2g + tid);
                     l2bs[tid] = __ldg(l2b + tid); w3s[tid] = __ldg(wq3 + tid); }
    const int m0 = (wid & 1) * 64, n0 = (wid >> 1) * 64, wn = wid >> 1;
    auto load3 = [&](int kc) {
        uint32_t st = sb + (kc % 3) * 49152;
        cp_tile<128>(st,         gX2, row0, 1024, kc * 64, tid);
        cp_tile<256>(st + 16384, gQ1, 0, 1024, kc * 64, tid);
        CP_COMMIT();
    };
    load3(0); load3(1);
    float c3[4][8][4];
    #pragma unroll
    for (int a = 0; a < 4; ++a)
        #pragma unroll
        for (int b = 0; b < 8; ++b)
            #pragma unroll
            for (int e = 0; e < 4; ++e) c3[a][b][e] = 0.f;
    #pragma unroll 1
    for (int kc = 0; kc < 16; ++kc) {
        if (kc < 14) CP_WAIT(1); else CP_WAIT(0);
        __syncthreads();
        if (kc + 2 < 16) load3(kc + 2);
        uint32_t st = sb + (kc % 3) * 49152;
        mma_chunk1<4, 4>(c3, st, st + 16384, m0, n0, lane);
    }
    cp_tile<128>(sb + K3_Q2A, gQ2, 0, 256, 0, tid);
    CP_COMMIT();
    #pragma unroll
    for (int mf = 0; mf < 4; ++mf)
        #pragma unroll
        for (int nf = 0; nf < 8; ++nf)
            #pragma unroll
            for (int e = 0; e < 4; ++e)
                c3[mf][nf][e] += bq1s[n0 + nf * 8 + q * 2 + (e & 1)];
    #pragma unroll
    for (int mf = 0; mf < 4; ++mf)
        #pragma unroll
        for (int s = 0; s < 2; ++s) {
            float sm1 = 0.f, sq = 0.f;
            #pragma unroll
            for (int nf = 0; nf < 8; ++nf) {
                float v0 = c3[mf][nf][s*2], v1 = c3[mf][nf][s*2+1];
                sm1 += v0 + v1; sq += v0 * v0 + v1 * v1;
            }
            sm1 += __shfl_xor_sync(~0u, sm1, 1); sm1 += __shfl_xor_sync(~0u, sm1, 2);
            sq  += __shfl_xor_sync(~0u, sq, 1);  sq  += __shfl_xor_sync(~0u, sq, 2);
            if (q == 0) {
                int r = m0 + mf * 16 + s * 8 + t4;
                PS[wn * 128 + r] = sm1; PQ[wn * 128 + r] = sq;
            }
        }
    __syncthreads();
    if (tid < 128) {
        float S  = PS[tid] + PS[128 + tid] + PS[256 + tid] + PS[384 + tid];
        float Q2 = PQ[tid] + PQ[128 + tid] + PQ[256 + tid] + PQ[384 + tid];
        float mu = S * (1.f / 256.f);
        MU[tid] = mu; RS[tid] = rsqrtf(Q2 * (1.f / 256.f) - mu * mu + 1e-5f);
    }
    __syncthreads();
    #pragma unroll
    for (int mf = 0; mf < 4; ++mf)
        #pragma unroll
        for (int s = 0; s < 2; ++s) {
            int r = m0 + mf * 16 + s * 8 + t4;
            float mu = MU[r], rs = RS[r];
            #pragma unroll
            for (int nf = 0; nf < 8; ++nf) {
                int col = n0 + nf * 8 + q * 2;
                float v0 = fmaxf((c3[mf][nf][s*2]   - mu) * rs * l1gs[col]   + l1bs[col],   0.f);
                float v1 = fmaxf((c3[mf][nf][s*2+1] - mu) * rs * l1gs[col+1] + l1bs[col+1], 0.f);
                int off = K3_H1 + ((col >> 6) << 14) + SWZ(r * 128 + (col & 63) * 2);
                *(uint32_t*)(smx + off) = pack_h2(__float2half_rn(v0), __float2half_rn(v1));
            }
        }
    const int m4 = (wid & 3) * 32, n4 = (wid >> 2) * 64, wn4 = wid >> 2;
    float c4[2][8][4];
    #pragma unroll
    for (int a = 0; a < 2; ++a)
        #pragma unroll
        for (int b = 0; b < 8; ++b)
            #pragma unroll
            for (int e = 0; e < 4; ++e) c4[a][b][e] = 0.f;
    #pragma unroll 1
    for (int qc = 0; qc < 4; ++qc) {
        CP_WAIT(0);
        __syncthreads();      // qc=0 barrier also publishes the H1 smem writes above
        if (qc + 1 < 4) {
            cp_tile<128>(sb + K3_Q2A + ((qc + 1) & 1) * 16384, gQ2, 0, 256, (qc + 1) * 64, tid);
            CP_COMMIT();
        }
        mma_chunk1<2, 4>(c4, sb + K3_H1 + qc * 16384, sb + K3_Q2A + (qc & 1) * 16384, m4, n4, lane);
    }
    #pragma unroll
    for (int mf = 0; mf < 2; ++mf)
        #pragma unroll
        for (int nf = 0; nf < 8; ++nf)
            #pragma unroll
            for (int e = 0; e < 4; ++e)
                c4[mf][nf][e] += bq2s[n4 + nf * 8 + q * 2 + (e & 1)];
    #pragma unroll
    for (int mf = 0; mf < 2; ++mf)
        #pragma unroll
        for (int s = 0; s < 2; ++s) {
            float sm1 = 0.f, sq = 0.f;
            #pragma unroll
            for (int nf = 0; nf < 8; ++nf) {
                float v0 = c4[mf][nf][s*2], v1 = c4[mf][nf][s*2+1];
                sm1 += v0 + v1; sq += v0 * v0 + v1 * v1;
            }
            sm1 += __shfl_xor_sync(~0u, sm1, 1); sm1 += __shfl_xor_sync(~0u, sm1, 2);
            sq  += __shfl_xor_sync(~0u, sq, 1);  sq  += __shfl_xor_sync(~0u, sq, 2);
            if (q == 0) {
                int r = m4 + mf * 16 + s * 8 + t4;
                PS[wn4 * 128 + r] = sm1; PQ[wn4 * 128 + r] = sq;
            }
        }
    __syncthreads();
    if (tid < 128) {
        float S  = PS[tid] + PS[128 + tid];
        float Q2 = PQ[tid] + PQ[128 + tid];
        float mu = S * (1.f / 128.f);
        MU[tid] = mu; RS[tid] = rsqrtf(Q2 * (1.f / 128.f) - mu * mu + 1e-5f);
    }
    __syncthreads();
    #pragma unroll
    for (int mf = 0; mf < 2; ++mf)
        #pragma unroll
        for (int s = 0; s < 2; ++s) {
            int r = m4 + mf * 16 + s * 8 + t4;
            float mu = MU[r], rs = RS[r];
            float d = 0.f;
            #pragma unroll
            for (int nf = 0; nf < 8; ++nf) {
                int col = n4 + nf * 8 + q * 2;
                float v0 = fmaxf((c4[mf][nf][s*2]   - mu) * rs * l2gs[col]   + l2bs[col],   0.f);
                float v1 = fmaxf((c4[mf][nf][s*2+1] - mu) * rs * l2gs[col+1] + l2bs[col+1], 0.f);
                d += v0 * w3s[col] + v1 * w3s[col + 1];
            }
            d += __shfl_xor_sync(~0u, d, 1); d += __shfl_xor_sync(~0u, d, 2);
            if (q == 0) PD[wn4 * 128 + r] = d;
        }
    __syncthreads();
    if (tid < 128) out[row0 + tid] = PD[tid] + PD[128 + tid] + __ldg(bq3);
}

extern "C" void kernel_launch(void* const* d_in, const int* in_sizes, int n_in,
                              void* d_out, int out_size) {
    const float* state  = (const float*)d_in[0];
    const float* action = (const float*)d_in[1];
    const float* W1  = (const float*)d_in[2];
    const float* b1  = (const float*)d_in[3];
    const float* g1  = (const float*)d_in[4];
    const float* W2  = (const float*)d_in[5];
    const float* b2  = (const float*)d_in[6];
    const float* g2  = (const float*)d_in[7];
    const float* Wq1 = (const float*)d_in[8];
    const float* bq1 = (const float*)d_in[9];
    const float* l1g = (const float*)d_in[10];
    const float* l1b = (const float*)d_in[11];
    const float* Wq2 = (const float*)d_in[12];
    const float* bq2 = (const float*)d_in[13];
    const float* l2g = (const float*)d_in[14];
    const float* l2b = (const float*)d_in[15];
    const float* Wq3 = (const float*)d_in[16];
    const float* bq3 = (const float*)d_in[17];
    float* out = (float*)d_out;
    int B = in_sizes[0] / 24;
    int tiles = B / 128;
    cudaFuncSetAttribute(k1, cudaFuncAttributeMaxDynamicSharedMemorySize, K1_SZ);
    cudaFuncSetAttribute(k2, cudaFuncAttributeMaxDynamicSharedMemorySize, K2_SZ);
    cudaFuncSetAttribute(k3, cudaFuncAttributeMaxDynamicSharedMemorySize, K3_SZ);
    prep<<<256, 256>>>(W1, W2, Wq1, Wq2);
    k1<<<tiles, 256, K1_SZ>>>(state, action, b1, g1);
    k2<<<tiles * 8, 256, K2_SZ>>>(b2, g2);
    k3<<<tiles, 256, K3_SZ>>>(bq1, l1g, l1b, bq2, l2g, l2b, Wq3, bq3, out);
}

// round 17
// speedup vs baseline: 1.1716x; 1.0280x over previous
#include <cuda_runtime.h>
#include <cuda_fp16.h>
#include <stdint.h>
#include <math.h>
typedef __half f16;

__device__ __align__(256) f16 gX1[(size_t)131072*1024];
__device__ __align__(256) f16 gX2[(size_t)131072*1024];
__device__ __align__(256) f16 gW1[1024*64];
__device__ __align__(256) f16 gW2[1024*1024];
__device__ __align__(256) f16 gQ1[256*1024];
__device__ __align__(256) f16 gQ2[128*256];

__device__ __forceinline__ uint32_t smem_u32(const void* p) {
    uint32_t a; asm("{ .reg .u64 t; cvta.to.shared.u64 t, %1; cvt.u32.u64 %0, t; }" : "=r"(a) : "l"(p));
    return a;
}
__device__ __forceinline__ void cpa16(uint32_t d, const void* s) {
    asm volatile("cp.async.cg.shared.global [%0], [%1], 16;" :: "r"(d), "l"(s));
}
#define CP_COMMIT() asm volatile("cp.async.commit_group;" ::: "memory")
#define CP_WAIT(n)  asm volatile("cp.async.wait_group %0;" :: "n"(n) : "memory")
__device__ __forceinline__ void ldm4(uint32_t* r, uint32_t a) {
    asm volatile("ldmatrix.sync.aligned.m8n8.x4.shared.b16 {%0,%1,%2,%3}, [%4];"
        : "=r"(r[0]), "=r"(r[1]), "=r"(r[2]), "=r"(r[3]) : "r"(a));
}
__device__ __forceinline__ void mma_f16(float* c, const uint32_t* a, const uint32_t* b) {
    asm volatile("mma.sync.aligned.m16n8k16.row.col.f32.f16.f16.f32 "
        "{%0,%1,%2,%3}, {%4,%5,%6,%7}, {%8,%9}, {%0,%1,%2,%3};"
        : "+f"(c[0]), "+f"(c[1]), "+f"(c[2]), "+f"(c[3])
        : "r"(a[0]), "r"(a[1]), "r"(a[2]), "r"(a[3]), "r"(b[0]), "r"(b[1]));
}
#define SWZ(x) ((x) ^ (((x) >> 3) & 0x70))
__device__ __forceinline__ uint32_t a_addr(uint32_t base, int r0, int kk, int lane) {
    return base + SWZ((r0 + (lane & 15)) * 128 + kk * 32 + ((lane >> 4) << 4));
}
__device__ __forceinline__ uint32_t b_addr(uint32_t base, int n0, int kk, int lane) {
    return base + SWZ((n0 + (lane & 7) + ((lane >> 4) << 3)) * 128 + kk * 32 + (((lane >> 3) & 1) << 4));
}
template<int R>
__device__ __forceinline__ void cp_tile(uint32_t dsm, const f16* g, long row0, int stride, int k0, int tid) {
    #pragma unroll
    for (int i = 0; i < R * 8 / 256; ++i) {
        int u = tid + i * 256, r = u >> 3, c = u & 7;
        cpa16(dsm + SWZ(r * 128 + c * 16), g + (row0 + r) * (long)stride + k0 + c * 8);
    }
}
__device__ __forceinline__ uint32_t pack_h2(f16 a, f16 b) {
    __half2 t; t.x = a; t.y = b; return *reinterpret_cast<uint32_t*>(&t);
}
__device__ __forceinline__ float tanh_fast(float x) {
    float y; asm("tanh.approx.f32 %0, %1;" : "=f"(y) : "f"(x)); return y;
}
// double-buffered-fragment fp16 MMA over one K64 slab (KK k-steps of 16)
template<int MF, int KK>
__device__ __forceinline__ void mma_chunkDB(float (&c)[MF][8][4], uint32_t bA, uint32_t bB,
                                            int m0, int n0, int lane) {
    uint32_t A[2][MF][4], B[2][4][4];
    #pragma unroll
    for (int mf = 0; mf < MF; ++mf) ldm4(A[0][mf], a_addr(bA, m0 + mf * 16, 0, lane));
    #pragma unroll
    for (int np = 0; np < 4; ++np) ldm4(B[0][np], b_addr(bB, n0 + np * 16, 0, lane));
    #pragma unroll
    for (int kk = 0; kk < KK; ++kk) {
        int cur = kk & 1, nxt = cur ^ 1;
        if (kk + 1 < KK) {
            #pragma unroll
            for (int mf = 0; mf < MF; ++mf) ldm4(A[nxt][mf], a_addr(bA, m0 + mf * 16, kk + 1, lane));
            #pragma unroll
            for (int np = 0; np < 4; ++np) ldm4(B[nxt][np], b_addr(bB, n0 + np * 16, kk + 1, lane));
        }
        #pragma unroll
        for (int np = 0; np < 4; ++np)
            #pragma unroll
            for (int mf = 0; mf < MF; ++mf)
                #pragma unroll
                for (int h = 0; h < 2; ++h)
                    mma_f16(c[mf][np * 2 + h], A[cur][mf], B[cur][np] + h * 2);
    }
}
__device__ __forceinline__ void epi_store(float (&c)[2][8][4], int m0, int gcol0, int lane,
        long grow0, const float* bias, const float* gate, f16* gout) {
    int t4 = lane >> 2, q = lane & 3;
    #pragma unroll
    for (int mf = 0; mf < 2; ++mf)
    #pragma unroll
    for (int s = 0; s < 2; ++s) {
        long gr = (grow0 + m0 + mf * 16 + s * 8 + t4) * 1024;
        #pragma unroll
        for (int nf = 0; nf < 8; ++nf) {
            int col = gcol0 + nf * 8 + q * 2;
            float g = gate[col >> 5];
            float v0 = tanh_fast(c[mf][nf][s * 2]     + bias[col])     * g;
            float v1 = tanh_fast(c[mf][nf][s * 2 + 1] + bias[col + 1]) * g;
            *(uint32_t*)(gout + gr + col) = pack_h2(__float2half_rn(v0), __float2half_rn(v1));
        }
    }
}

__global__ void prep(const float* __restrict__ W1, const float* __restrict__ W2,
                     const float* __restrict__ Wq1, const float* __restrict__ Wq2) {
    __shared__ float ts[32][33];
    int gt = blockIdx.x * blockDim.x + threadIdx.x, gs = gridDim.x * blockDim.x;
    int tid = threadIdx.x;
    for (int t = blockIdx.x; t < 1024; t += gridDim.x) {
        int kt = (t >> 5) * 32, nt_ = (t & 31) * 32;
        #pragma unroll
        for (int j = tid; j < 1024; j += 256) {
            int r = j >> 5, cn = j & 31;
            ts[r][cn] = W2[(size_t)(nt_ >> 5) * 32768 + (kt + r) * 32 + cn];
        }
        __syncthreads();
        #pragma unroll
        for (int j = tid; j < 1024; j += 256) {
            int rn = j >> 5, ck = j & 31;
            gW2[(size_t)(nt_ + rn) * 1024 + kt + ck] = __float2half_rn(ts[ck][rn]);
        }
        __syncthreads();
    }
    for (int i = gt; i < 256 * 1024; i += gs) {
        int qq = i >> 10, n = i & 1023;
        gQ1[i] = __float2half_rn(Wq1[n * 256 + qq]);
    }
    for (int i = gt; i < 128 * 256; i += gs) {
        int o = i >> 8, qq = i & 255;
        gQ2[i] = __float2half_rn(Wq2[qq * 128 + o]);
    }
    for (int i = gt; i < 1024 * 64; i += gs) {
        int n = i >> 6, d = i & 63;
        gW1[i] = __float2half_rn((d < 32) ? W1[(n >> 5) * 1024 + d * 32 + (n & 31)] : 0.0f);
    }
}

// ---- k1 ----
#define K1_B1S 49152
#define K1_G1S 53248
#define K1_SZ  53376
__global__ __launch_bounds__(256,2) void k1(const float* __restrict__ state, const float* __restrict__ action,
                                            const float* __restrict__ b1, const float* __restrict__ g1) {
    extern __shared__ char smx[];
    const uint32_t sb = smem_u32(smx);
    const int tid = threadIdx.x, lane = tid & 31, wid = tid >> 5;
    const long row0 = (long)blockIdx.x * 128;
    float* b1s = (float*)(smx + K1_B1S);
    float* g1s = (float*)(smx + K1_G1S);
    for (int i = tid; i < 1024; i += 256) b1s[i] = __ldg(b1 + i);
    if (tid < 32) g1s[tid] = 1.f / (1.f + expf(-__ldg(g1 + tid)));
    for (int i = tid; i < 4096; i += 256) ((uint32_t*)smx)[i] = 0;
    __syncthreads();
    for (int i = tid; i < 4096; i += 256) {
        int r = i >> 5, d = i & 31;
        float v = (d < 24) ? __ldg(state + (row0 + r) * 24 + d)
                           : __ldg(action + (row0 + r) * 8 + (d - 24));
        *(f16*)(smx + SWZ(r * 128 + d * 2)) = __float2half_rn(v);
    }
    __syncthreads();
    const int m0 = (wid & 3) * 32, n0 = (wid >> 2) * 64;
    cp_tile<128>(sb + 16384, gW1, 0, 64, 0, tid);
    CP_COMMIT();
    #pragma unroll 1
    for (int nt = 0; nt < 8; ++nt) {
        CP_WAIT(0);
        __syncthreads();
        if (nt + 1 < 8) {
            cp_tile<128>(sb + 16384 + ((nt + 1) & 1) * 16384, gW1, (long)(nt + 1) * 128, 64, 0, tid);
            CP_COMMIT();
        }
        uint32_t bs = sb + 16384 + (nt & 1) * 16384;
        float c[2][8][4];
        #pragma unroll
        for (int a = 0; a < 2; ++a)
            #pragma unroll
            for (int b = 0; b < 8; ++b)
                #pragma unroll
                for (int e = 0; e < 4; ++e) c[a][b][e] = 0.f;
        mma_chunkDB<2, 2>(c, sb, bs, m0, n0, lane);
        epi_store(c, m0, nt * 128 + n0, lane, row0, b1s, g1s, gX1);
    }
}

// ---- k2: 3 stages x 32KB ----
#define K2_B2S 98304
#define K2_G2S 102400
#define K2_SZ  102528
__global__ __launch_bounds__(256,2) void k2(const float* __restrict__ b2, const float* __restrict__ g2) {
    extern __shared__ char smx[];
    const uint32_t sb = smem_u32(smx);
    const int tid = threadIdx.x, lane = tid & 31, wid = tid >> 5;
    const long row0 = (long)(blockIdx.x >> 3) * 128;
    const int nt = blockIdx.x & 7;
    float* b2s = (float*)(smx + K2_B2S);
    float* g2s = (float*)(smx + K2_G2S);
    for (int i = tid; i < 1024; i += 256) b2s[i] = __ldg(b2 + i);
    if (tid < 32) g2s[tid] = 1.f / (1.f + expf(-__ldg(g2 + tid)));
    const int m0 = (wid & 3) * 32, n0 = (wid >> 2) * 64;
    auto load = [&](int kc) {
        uint32_t st = sb + (kc % 3) * 32768;
        cp_tile<128>(st,         gX1, row0, 1024, kc * 64, tid);
        cp_tile<128>(st + 16384, gW2, (long)nt * 128, 1024, kc * 64, tid);
        CP_COMMIT();
    };
    load(0); load(1);
    float c[2][8][4];
    #pragma unroll
    for (int a = 0; a < 2; ++a)
        #pragma unroll
        for (int b = 0; b < 8; ++b)
            #pragma unroll
            for (int e = 0; e < 4; ++e) c[a][b][e] = 0.f;
    #pragma unroll 1
    for (int kc = 0; kc < 16; ++kc) {
        if (kc < 14) CP_WAIT(1); else CP_WAIT(0);
        __syncthreads();
        if (kc + 2 < 16) load(kc + 2);
        uint32_t st = sb + (kc % 3) * 32768;
        mma_chunkDB<2, 4>(c, st, st + 16384, m0, n0, lane);
    }
    epi_store(c, m0, nt * 128 + n0, lane, row0, b2s, g2s, gX2);
}

// ---- k3 ----
#define K3_H1  147456
#define K3_Q2A 49152
#define K3_BQ1 212992
#define K3_L1G 214016
#define K3_L1B 215040
#define K3_BQ2 216064
#define K3_L2G 216576
#define K3_L2B 217088
#define K3_W3  217600
#define K3_PS  218112
#define K3_PQ  220160
#define K3_MU  222208
#define K3_RS  222720
#define K3_PD  223232
#define K3_SZ  225280
__global__ __launch_bounds__(256,1) void k3(const float* __restrict__ bq1, const float* __restrict__ l1g, const float* __restrict__ l1b,
                                            const float* __restrict__ bq2, const float* __restrict__ l2g, const float* __restrict__ l2b,
                                            const float* __restrict__ wq3, const float* __restrict__ bq3, float* __restrict__ out) {
    extern __shared__ char smx[];
    const uint32_t sb = smem_u32(smx);
    const int tid = threadIdx.x, lane = tid & 31, wid = tid >> 5;
    const int t4 = lane >> 2, q = lane & 3;
    const long row0 = (long)blockIdx.x * 128;
    float* bq1s = (float*)(smx + K3_BQ1); float* l1gs = (float*)(smx + K3_L1G);
    float* l1bs = (float*)(smx + K3_L1B); float* bq2s = (float*)(smx + K3_BQ2);
    float* l2gs = (float*)(smx + K3_L2G); float* l2bs = (float*)(smx + K3_L2B);
    float* w3s  = (float*)(smx + K3_W3);
    float* PS = (float*)(smx + K3_PS); float* PQ = (float*)(smx + K3_PQ);
    float* MU = (float*)(smx + K3_MU); float* RS = (float*)(smx + K3_RS);
    float* PD = (float*)(smx + K3_PD);
    bq1s[tid] = __ldg(bq1 + tid); l1gs[tid] = __ldg(l1g + tid); l1bs[tid] = __ldg(l1b + tid);
    if (tid < 128) { bq2s[tid] = __ldg(bq2 + tid); l2gs[tid] = __ldg(l2g + tid);
                     l2bs[tid] = __ldg(l2b + tid); w3s[tid] = __ldg(wq3 + tid); }
    const int m0 = (wid & 1) * 64, n0 = (wid >> 1) * 64, wn = wid >> 1;
    auto load3 = [&](int kc) {
        uint32_t st = sb + (kc % 3) * 49152;
        cp_tile<128>(st,         gX2, row0, 1024, kc * 64, tid);
        cp_tile<256>(st + 16384, gQ1, 0, 1024, kc * 64, tid);
        CP_COMMIT();
    };
    load3(0); load3(1);
    float c3[4][8][4];
    #pragma unroll
    for (int a = 0; a < 4; ++a)
        #pragma unroll
        for (int b = 0; b < 8; ++b)
            #pragma unroll
            for (int e = 0; e < 4; ++e) c3[a][b][e] = 0.f;
    #pragma unroll 1
    for (int kc = 0; kc < 16; ++kc) {
        if (kc < 14) CP_WAIT(1); else CP_WAIT(0);
        __syncthreads();
        if (kc + 2 < 16) load3(kc + 2);
        uint32_t st = sb + (kc % 3) * 49152;
        mma_chunkDB<4, 4>(c3, st, st + 16384, m0, n0, lane);
    }
    cp_tile<128>(sb + K3_Q2A, gQ2, 0, 256, 0, tid);
    CP_COMMIT();
    #pragma unroll
    for (int mf = 0; mf < 4; ++mf)
        #pragma unroll
        for (int nf = 0; nf < 8; ++nf)
            #pragma unroll
            for (int e = 0; e < 4; ++e)
                c3[mf][nf][e] += bq1s[n0 + nf * 8 + q * 2 + (e & 1)];
    #pragma unroll
    for (int mf = 0; mf < 4; ++mf)
        #pragma unroll
        for (int s = 0; s < 2; ++s) {
            float sm1 = 0.f, sq = 0.f;
            #pragma unroll
            for (int nf = 0; nf < 8; ++nf) {
                float v0 = c3[mf][nf][s*2], v1 = c3[mf][nf][s*2+1];
                sm1 += v0 + v1; sq += v0 * v0 + v1 * v1;
            }
            sm1 += __shfl_xor_sync(~0u, sm1, 1); sm1 += __shfl_xor_sync(~0u, sm1, 2);
            sq  += __shfl_xor_sync(~0u, sq, 1);  sq  += __shfl_xor_sync(~0u, sq, 2);
            if (q == 0) {
                int r = m0 + mf * 16 + s * 8 + t4;
                PS[wn * 128 + r] = sm1; PQ[wn * 128 + r] = sq;
            }
        }
    __syncthreads();
    if (tid < 128) {
        float S  = PS[tid] + PS[128 + tid] + PS[256 + tid] + PS[384 + tid];
        float Q2 = PQ[tid] + PQ[128 + tid] + PQ[256 + tid] + PQ[384 + tid];
        float mu = S * (1.f / 256.f);
        MU[tid] = mu; RS[tid] = rsqrtf(Q2 * (1.f / 256.f) - mu * mu + 1e-5f);
    }
    __syncthreads();
    #pragma unroll
    for (int mf = 0; mf < 4; ++mf)
        #pragma unroll
        for (int s = 0; s < 2; ++s) {
            int r = m0 + mf * 16 + s * 8 + t4;
            float mu = MU[r], rs = RS[r];
            #pragma unroll
            for (int nf = 0; nf < 8; ++nf) {
                int col = n0 + nf * 8 + q * 2;
                float v0 = fmaxf((c3[mf][nf][s*2]   - mu) * rs * l1gs[col]   + l1bs[col],   0.f);
                float v1 = fmaxf((c3[mf][nf][s*2+1] - mu) * rs * l1gs[col+1] + l1bs[col+1], 0.f);
                int off = K3_H1 + ((col >> 6) << 14) + SWZ(r * 128 + (col & 63) * 2);
                *(uint32_t*)(smx + off) = pack_h2(__float2half_rn(v0), __float2half_rn(v1));
            }
        }
    const int m4 = (wid & 3) * 32, n4 = (wid >> 2) * 64, wn4 = wid >> 2;
    float c4[2][8][4];
    #pragma unroll
    for (int a = 0; a < 2; ++a)
        #pragma unroll
        for (int b = 0; b < 8; ++b)
            #pragma unroll
            for (int e = 0; e < 4; ++e) c4[a][b][e] = 0.f;
    #pragma unroll 1
    for (int qc = 0; qc < 4; ++qc) {
        CP_WAIT(0);
        __syncthreads();      // qc=0 barrier also publishes the H1 smem writes above
        if (qc + 1 < 4) {
            cp_tile<128>(sb + K3_Q2A + ((qc + 1) & 1) * 16384, gQ2, 0, 256, (qc + 1) * 64, tid);
            CP_COMMIT();
        }
        mma_chunkDB<2, 4>(c4, sb + K3_H1 + qc * 16384, sb + K3_Q2A + (qc & 1) * 16384, m4, n4, lane);
    }
    #pragma unroll
    for (int mf = 0; mf < 2; ++mf)
        #pragma unroll
        for (int nf = 0; nf < 8; ++nf)
            #pragma unroll
            for (int e = 0; e < 4; ++e)
                c4[mf][nf][e] += bq2s[n4 + nf * 8 + q * 2 + (e & 1)];
    #pragma unroll
    for (int mf = 0; mf < 2; ++mf)
        #pragma unroll
        for (int s = 0; s < 2; ++s) {
            float sm1 = 0.f, sq = 0.f;
            #pragma unroll
            for (int nf = 0; nf < 8; ++nf) {
                float v0 = c4[mf][nf][s*2], v1 = c4[mf][nf][s*2+1];
                sm1 += v0 + v1; sq += v0 * v0 + v1 * v1;
            }
            sm1 += __shfl_xor_sync(~0u, sm1, 1); sm1 += __shfl_xor_sync(~0u, sm1, 2);
            sq  += __shfl_xor_sync(~0u, sq, 1);  sq  += __shfl_xor_sync(~0u, sq, 2);
            if (q == 0) {
                int r = m4 + mf * 16 + s * 8 + t4;
                PS[wn4 * 128 + r] = sm1; PQ[wn4 * 128 + r] = sq;
            }
        }
    __syncthreads();
    if (tid < 128) {
        float S  = PS[tid] + PS[128 + tid];
        float Q2 = PQ[tid] + PQ[128 + tid];
        float mu = S * (1.f / 128.f);
        MU[tid] = mu; RS[tid] = rsqrtf(Q2 * (1.f / 128.f) - mu * mu + 1e-5f);
    }
    __syncthreads();
    #pragma unroll
    for (int mf = 0; mf < 2; ++mf)
        #pragma unroll
        for (int s = 0; s < 2; ++s) {
            int r = m4 + mf * 16 + s * 8 + t4;
            float mu = MU[r], rs = RS[r];
            float d = 0.f;
            #pragma unroll
            for (int nf = 0; nf < 8; ++nf) {
                int col = n4 + nf * 8 + q * 2;
                float v0 = fmaxf((c4[mf][nf][s*2]   - mu) * rs * l2gs[col]   + l2bs[col],   0.f);
                float v1 = fmaxf((c4[mf][nf][s*2+1] - mu) * rs * l2gs[col+1] + l2bs[col+1], 0.f);
                d += v0 * w3s[col] + v1 * w3s[col + 1];
            }
            d += __shfl_xor_sync(~0u, d, 1); d += __shfl_xor_sync(~0u, d, 2);
            if (q == 0) PD[wn4 * 128 + r] = d;
        }
    __syncthreads();
    if (tid < 128) out[row0 + tid] = PD[tid] + PD[128 + tid] + __ldg(bq3);
}

extern "C" void kernel_launch(void* const* d_in, const int* in_sizes, int n_in,
                              void* d_out, int out_size) {
    const float* state  = (const float*)d_in[0];
    const float* action = (const float*)d_in[1];
    const float* W1  = (const float*)d_in[2];
    const float* b1  = (const float*)d_in[3];
    const float* g1  = (const float*)d_in[4];
    const float* W2  = (const float*)d_in[5];
    const float* b2  = (const float*)d_in[6];
    const float* g2  = (const float*)d_in[7];
    const float* Wq1 = (const float*)d_in[8];
    const float* bq1 = (const float*)d_in[9];
    const float* l1g = (const float*)d_in[10];
    const float* l1b = (const float*)d_in[11];
    const float* Wq2 = (const float*)d_in[12];
    const float* bq2 = (const float*)d_in[13];
    const float* l2g = (const float*)d_in[14];
    const float* l2b = (const float*)d_in[15];
    const float* Wq3 = (const float*)d_in[16];
    const float* bq3 = (const float*)d_in[17];
    float* out = (float*)d_out;
    int B = in_sizes[0] / 24;
    int tiles = B / 128;
    cudaFuncSetAttribute(k1, cudaFuncAttributeMaxDynamicSharedMemorySize, K1_SZ);
    cudaFuncSetAttribute(k2, cudaFuncAttributeMaxDynamicSharedMemorySize, K2_SZ);
    cudaFuncSetAttribute(k3, cudaFuncAttributeMaxDynamicSharedMemorySize, K3_SZ);
    prep<<<256, 256>>>(W1, W2, Wq1, Wq2);
    k1<<<tiles, 256, K1_SZ>>>(state, action, b1, g1);
    k2<<<tiles * 8, 256, K2_SZ>>>(b2, g2);
    k3<<<tiles, 256, K3_SZ>>>(bq1, l1g, l1b, bq2, l2g, l2b, Wq3, bq3, out);
}